// round 1
// baseline (speedup 1.0000x reference)
#include <cuda_runtime.h>
#include <math.h>

// ---------------------------------------------------------------------------
// AttentionEncoderModel: MLP funnel -> pre-linear + positional -> 8 transformer
// blocks (pre-LN, causal MHA H=8 DH=32, GELU MLP) -> out proj -> global standardize
// Baseline: fp32 tiled SGEMM (128x128x8, 8x8/thread), fused epilogues.
// ---------------------------------------------------------------------------

#define BM 128
#define BN 128
#define BK 8
#define TM 8
#define TN 8

// scratch (device globals; allocation inside kernel_launch is forbidden)
__device__ float g_a[4096 * 4096];   // 64 MB ping
__device__ float g_b[4096 * 2048];   // 32 MB pong
__device__ float g_x[4096 * 256];    // residual stream
__device__ float g_xn[4096 * 256];   // LN1 output
__device__ float g_c[4096 * 768];    // qkv
__device__ float g_h[4096 * 1024];   // MLP hidden
__device__ double g_sum_d, g_sumsq_d;

// ACT: 0=none 1=relu 2=tanh 3=gelu(exact)
template <int ACT>
__global__ __launch_bounds__(256, 2) void sgemm_k(
    const float* __restrict__ A, const float* __restrict__ W,
    const float* __restrict__ bias, const float* __restrict__ res,
    const float* __restrict__ pos, float* __restrict__ C,
    int M, int N, int K)
{
    __shared__ float As[BK][BM];
    __shared__ float Bs[BK][BN];

    int tid = threadIdx.x;
    int bm = blockIdx.y * BM;
    int bn = blockIdx.x * BN;
    int ty = tid >> 4, tx = tid & 15;
    int m0 = ty * TM, n0 = tx * TN;

    float acc[TM][TN] = {};

    int arow = tid >> 1;
    int acol = (tid & 1) * 4;
    int brow = tid >> 5;
    int bcol = (tid & 31) * 4;

    const float* Aptr = A + (size_t)(bm + arow) * K + acol;
    const float* Wptr = W + (size_t)brow * N + bn + bcol;

    for (int k0 = 0; k0 < K; k0 += BK) {
        float4 av = *(const float4*)(Aptr + k0);
        As[acol + 0][arow] = av.x;
        As[acol + 1][arow] = av.y;
        As[acol + 2][arow] = av.z;
        As[acol + 3][arow] = av.w;
        float4 bv = *(const float4*)(Wptr + (size_t)k0 * N);
        *(float4*)(&Bs[brow][bcol]) = bv;
        __syncthreads();

#pragma unroll
        for (int k = 0; k < BK; k++) {
            float a[TM], b[TN];
#pragma unroll
            for (int i = 0; i < TM; i++) a[i] = As[k][m0 + i];
#pragma unroll
            for (int j = 0; j < TN; j++) b[j] = Bs[k][n0 + j];
#pragma unroll
            for (int i = 0; i < TM; i++)
#pragma unroll
                for (int j = 0; j < TN; j++)
                    acc[i][j] = fmaf(a[i], b[j], acc[i][j]);
        }
        __syncthreads();
    }

#pragma unroll
    for (int i = 0; i < TM; i++) {
        int m = bm + m0 + i;
#pragma unroll
        for (int j = 0; j < TN; j++) {
            int n = bn + n0 + j;
            float v = acc[i][j] + bias[n];
            if (ACT == 1) v = fmaxf(v, 0.0f);
            else if (ACT == 2) v = tanhf(v);
            else if (ACT == 3) v = 0.5f * v * (1.0f + erff(v * 0.70710678118654752f));
            if (res) v += res[(size_t)m * N + n];
            if (pos) v += pos[(size_t)(m & 511) * N + n];  // S=512
            C[(size_t)m * N + n] = v;
        }
    }
}

// LayerNorm over last dim (D=256), one block per row, 256 threads.
__global__ void layernorm_k(const float* __restrict__ x, const float* __restrict__ g,
                            const float* __restrict__ b, float* __restrict__ y)
{
    int r = blockIdx.x, t = threadIdx.x;
    __shared__ float red[256];
    float v = x[(size_t)r * 256 + t];
    red[t] = v;
    __syncthreads();
    for (int s = 128; s > 0; s >>= 1) {
        if (t < s) red[t] += red[t + s];
        __syncthreads();
    }
    float mean = red[0] * (1.0f / 256.0f);
    __syncthreads();
    float d = v - mean;
    red[t] = d * d;
    __syncthreads();
    for (int s = 128; s > 0; s >>= 1) {
        if (t < s) red[t] += red[t + s];
        __syncthreads();
    }
    float var = red[0] * (1.0f / 256.0f);
    y[(size_t)r * 256 + t] = d * rsqrtf(var + 1e-5f) * g[t] + b[t];
}

// Causal attention. c: [B*S, 768] (q|k|v interleaved per row), x: [B*S, 256] (+=).
// One block per (b, h, query i), 128 threads. S=512, H=8, DH=32.
__global__ void attn_k(const float* __restrict__ c, float* __restrict__ x)
{
    const int S = 512, DH = 32, TD = 768;
    int i  = blockIdx.x & (S - 1);
    int bh = blockIdx.x >> 9;
    int b  = bh >> 3;
    int h  = bh & 7;
    int tid = threadIdx.x;

    __shared__ float q[DH];
    __shared__ float sc[512];
    __shared__ float red[128];
    __shared__ float wacc[4][DH];

    const float* base = c + (size_t)(b * S) * TD;
    if (tid < DH) q[tid] = base[(size_t)i * TD + h * DH + tid];
    __syncthreads();

    const float scale = 0.17677669529663687f;  // 1/sqrt(32)

    float lmax = -1e30f;
    for (int j = tid; j <= i; j += 128) {
        const float* kr = base + (size_t)j * TD + 256 + h * DH;
        float s0 = 0.0f;
#pragma unroll
        for (int d = 0; d < DH; d++) s0 = fmaf(q[d], kr[d], s0);
        s0 *= scale;
        sc[j] = s0;
        lmax = fmaxf(lmax, s0);
    }
    red[tid] = lmax;
    __syncthreads();
    for (int s = 64; s > 0; s >>= 1) {
        if (tid < s) red[tid] = fmaxf(red[tid], red[tid + s]);
        __syncthreads();
    }
    float mx = red[0];
    __syncthreads();

    float acc[DH];
#pragma unroll
    for (int d = 0; d < DH; d++) acc[d] = 0.0f;
    float lsum = 0.0f;
    for (int j = tid; j <= i; j += 128) {
        float p = expf(sc[j] - mx);
        lsum += p;
        const float* vr = base + (size_t)j * TD + 512 + h * DH;
#pragma unroll
        for (int d = 0; d < DH; d++) acc[d] = fmaf(p, vr[d], acc[d]);
    }
    red[tid] = lsum;
    __syncthreads();
    for (int s = 64; s > 0; s >>= 1) {
        if (tid < s) red[tid] += red[tid + s];
        __syncthreads();
    }
    float sum = red[0];

#pragma unroll
    for (int d = 0; d < DH; d++) {
        float v = acc[d];
#pragma unroll
        for (int o = 16; o > 0; o >>= 1) v += __shfl_xor_sync(0xffffffffu, v, o);
        if ((tid & 31) == 0) wacc[tid >> 5][d] = v;
    }
    __syncthreads();
    if (tid < DH) {
        float v = wacc[0][tid] + wacc[1][tid] + wacc[2][tid] + wacc[3][tid];
        x[(size_t)(b * S + i) * 256 + h * DH + tid] += v / sum;
    }
}

__global__ void zero_stats_k() { g_sum_d = 0.0; g_sumsq_d = 0.0; }

__global__ void stats_k(const float* __restrict__ e, int n)
{
    double s = 0.0, ss = 0.0;
    for (int i = blockIdx.x * blockDim.x + threadIdx.x; i < n;
         i += gridDim.x * blockDim.x) {
        double v = (double)e[i];
        s += v;
        ss += v * v;
    }
    for (int o = 16; o > 0; o >>= 1) {
        s  += __shfl_xor_sync(0xffffffffu, s, o);
        ss += __shfl_xor_sync(0xffffffffu, ss, o);
    }
    __shared__ double rs[8], rss[8];
    int w = threadIdx.x >> 5, l = threadIdx.x & 31;
    if (l == 0) { rs[w] = s; rss[w] = ss; }
    __syncthreads();
    if (threadIdx.x == 0) {
        double S = 0.0, SS = 0.0;
        int nw = blockDim.x >> 5;
        for (int i = 0; i < nw; i++) { S += rs[i]; SS += rss[i]; }
        atomicAdd(&g_sum_d, S);
        atomicAdd(&g_sumsq_d, SS);
    }
}

__global__ void normfinal_k(float* e, int n)
{
    double mean = g_sum_d / (double)n;
    double var = (g_sumsq_d - (double)n * mean * mean) / (double)(n - 1);
    double inv = rsqrt(var);
    for (int i = blockIdx.x * blockDim.x + threadIdx.x; i < n;
         i += gridDim.x * blockDim.x) {
        e[i] = (float)(((double)e[i] - mean) * inv + 1e-10);
    }
}

extern "C" void kernel_launch(void* const* d_in, const int* in_sizes, int n_in,
                              void* d_out, int out_size)
{
    const float* state = (const float*)d_in[0];
    const float* fc1w = (const float*)d_in[1];
    const float* fc1b = (const float*)d_in[2];
    const float* fc2w = (const float*)d_in[3];
    const float* fc2b = (const float*)d_in[4];
    const float* fc3w = (const float*)d_in[5];
    const float* fc3b = (const float*)d_in[6];
    const float* fc4w = (const float*)d_in[7];
    const float* fc4b = (const float*)d_in[8];
    const float* fc5w = (const float*)d_in[9];
    const float* fc5b = (const float*)d_in[10];
    const float* prew = (const float*)d_in[11];
    const float* preb = (const float*)d_in[12];
    const float* posw = (const float*)d_in[13];
    const float* encw = (const float*)d_in[14];
    const float* encb = (const float*)d_in[15];
    const float* ln1g = (const float*)d_in[16];
    const float* ln1b = (const float*)d_in[17];
    const float* ln2g = (const float*)d_in[18];
    const float* ln2b = (const float*)d_in[19];
    const float* rw1  = (const float*)d_in[20];
    const float* rb1  = (const float*)d_in[21];
    const float* rw2  = (const float*)d_in[22];
    const float* rb2  = (const float*)d_in[23];
    const float* outw = (const float*)d_in[24];
    const float* outb = (const float*)d_in[25];
    float* out = (float*)d_out;

    float *ga, *gb, *gx, *gxn, *gc, *gh;
    cudaGetSymbolAddress((void**)&ga,  g_a);
    cudaGetSymbolAddress((void**)&gb,  g_b);
    cudaGetSymbolAddress((void**)&gx,  g_x);
    cudaGetSymbolAddress((void**)&gxn, g_xn);
    cudaGetSymbolAddress((void**)&gc,  g_c);
    cudaGetSymbolAddress((void**)&gh,  g_h);

    const int M = 4096;  // B*S

    // MLP funnel
    sgemm_k<1><<<dim3(32, 32), 256>>>(state, fc1w, fc1b, nullptr, nullptr, ga, M, 4096, 4096);
    sgemm_k<1><<<dim3(16, 32), 256>>>(ga, fc2w, fc2b, nullptr, nullptr, gb, M, 2048, 4096);
    sgemm_k<1><<<dim3(8, 32), 256>>>(gb, fc3w, fc3b, nullptr, nullptr, ga, M, 1024, 2048);
    sgemm_k<1><<<dim3(4, 32), 256>>>(ga, fc4w, fc4b, nullptr, nullptr, gb, M, 512, 1024);
    sgemm_k<2><<<dim3(2, 32), 256>>>(gb, fc5w, fc5b, nullptr, nullptr, ga, M, 256, 512);
    // pre-linear + positional
    sgemm_k<0><<<dim3(2, 32), 256>>>(ga, prew, preb, nullptr, posw, gx, M, 256, 256);

    // transformer blocks
    for (int l = 0; l < 8; l++) {
        layernorm_k<<<4096, 256>>>(gx, ln1g + l * 256, ln1b + l * 256, gxn);
        sgemm_k<0><<<dim3(6, 32), 256>>>(gxn, encw + (size_t)l * 256 * 768,
                                         encb + l * 768, nullptr, nullptr, gc, M, 768, 256);
        attn_k<<<32768, 128>>>(gc, gx);                  // x += attn
        layernorm_k<<<4096, 256>>>(gx, ln2g + l * 256, ln2b + l * 256, gx);
        sgemm_k<3><<<dim3(8, 32), 256>>>(gx, rw1 + (size_t)l * 256 * 1024,
                                         rb1 + l * 1024, nullptr, nullptr, gh, M, 1024, 256);
        sgemm_k<0><<<dim3(2, 32), 256>>>(gh, rw2 + (size_t)l * 1024 * 256,
                                         rb2 + l * 256, gx, nullptr, gx, M, 256, 1024);
    }

    // output projection + global standardization
    sgemm_k<0><<<dim3(1, 32), 256>>>(gx, outw, outb, nullptr, nullptr, out, M, 128, 256);
    zero_stats_k<<<1, 1>>>();
    stats_k<<<512, 256>>>(out, 4096 * 128);
    normfinal_k<<<512, 256>>>(out, 4096 * 128);
}

// round 2
// speedup vs baseline: 4.8195x; 4.8195x over previous
#include <cuda_runtime.h>
#include <math.h>
#include <stdint.h>

// ---------------------------------------------------------------------------
// AttentionEncoderModel on GB300.
// R2: tf32 mma.sync for fc1-fc4, flash attention, 64-tile fp32 for small GEMMs.
// ---------------------------------------------------------------------------

// scratch
__device__ float g_a[4096 * 4096];
__device__ float g_b[4096 * 2048];
__device__ float g_x[4096 * 256];
__device__ float g_xn[4096 * 256];
__device__ float g_c[4096 * 768];
__device__ float g_h[4096 * 1024];
__device__ double g_sum_d, g_sumsq_d;

// ===========================================================================
// tf32 tensor-core GEMM: C = relu(A[M,K] @ W[K,N] + bias), tiles 128x128x32.
// 256 threads = 8 warps (2x4), warp tile 64x32, mma m16n8k8.
// ===========================================================================
__device__ __forceinline__ uint32_t f2tf32(float f) {
    uint32_t u;
    asm("cvt.rna.tf32.f32 %0, %1;" : "=r"(u) : "f"(f));
    return u;
}

#define AS(b, r, k) As_[(b) * (128 * 36) + (r) * 36 + (k)]
#define BS(b, r, n) Bs_[(b) * (32 * 136) + (r) * 136 + (n)]

__global__ __launch_bounds__(256) void tgemm_relu_k(
    const float* __restrict__ A, const float* __restrict__ W,
    const float* __restrict__ bias, float* __restrict__ C,
    int M, int N, int K)
{
    extern __shared__ float dynsmem[];
    float* As_ = dynsmem;                    // [2][128][36]
    float* Bs_ = dynsmem + 2 * 128 * 36;     // [2][32][136]

    int tid = threadIdx.x;
    int lane = tid & 31, wid = tid >> 5;
    int wm = wid >> 2, wn = wid & 3;         // 2 x 4 warps
    int m0 = blockIdx.y * 128, n0 = blockIdx.x * 128;

    float acc[4][4][4];
#pragma unroll
    for (int i = 0; i < 4; i++)
#pragma unroll
        for (int j = 0; j < 4; j++)
#pragma unroll
            for (int r = 0; r < 4; r++) acc[i][j][r] = 0.0f;

    int arow = tid >> 3;              // 0..31 (+32r)
    int acol = (tid & 7) * 4;
    int brow = tid >> 5;              // 0..7 (+8r)
    int bcol = (tid & 31) * 4;

    int ntiles = K >> 5;

    // preload tile 0
    {
#pragma unroll
        for (int r = 0; r < 4; r++) {
            float4 av = *(const float4*)(A + (size_t)(m0 + arow + r * 32) * K + acol);
            AS(0, arow + r * 32, acol + 0) = __uint_as_float(f2tf32(av.x));
            AS(0, arow + r * 32, acol + 1) = __uint_as_float(f2tf32(av.y));
            AS(0, arow + r * 32, acol + 2) = __uint_as_float(f2tf32(av.z));
            AS(0, arow + r * 32, acol + 3) = __uint_as_float(f2tf32(av.w));
            float4 bv = *(const float4*)(W + (size_t)(brow + r * 8) * N + n0 + bcol);
            BS(0, brow + r * 8, bcol + 0) = __uint_as_float(f2tf32(bv.x));
            BS(0, brow + r * 8, bcol + 1) = __uint_as_float(f2tf32(bv.y));
            BS(0, brow + r * 8, bcol + 2) = __uint_as_float(f2tf32(bv.z));
            BS(0, brow + r * 8, bcol + 3) = __uint_as_float(f2tf32(bv.w));
        }
    }
    __syncthreads();

    for (int t = 0; t < ntiles; t++) {
        int cur = t & 1;
        float4 ar[4], br[4];
        if (t + 1 < ntiles) {
            int kbase = (t + 1) * 32;
#pragma unroll
            for (int r = 0; r < 4; r++) {
                ar[r] = *(const float4*)(A + (size_t)(m0 + arow + r * 32) * K + kbase + acol);
                br[r] = *(const float4*)(W + (size_t)(kbase + brow + r * 8) * N + n0 + bcol);
            }
        }

#pragma unroll
        for (int ks = 0; ks < 4; ks++) {
            int kk = ks * 8;
            uint32_t af[4][4], bf[4][2];
#pragma unroll
            for (int am = 0; am < 4; am++) {
                int row = wm * 64 + am * 16 + (lane >> 2);
                int k = kk + (lane & 3);
                af[am][0] = __float_as_uint(AS(cur, row, k));
                af[am][1] = __float_as_uint(AS(cur, row + 8, k));
                af[am][2] = __float_as_uint(AS(cur, row, k + 4));
                af[am][3] = __float_as_uint(AS(cur, row + 8, k + 4));
            }
#pragma unroll
            for (int an = 0; an < 4; an++) {
                int col = wn * 32 + an * 8 + (lane >> 2);
                int k = kk + (lane & 3);
                bf[an][0] = __float_as_uint(BS(cur, k, col));
                bf[an][1] = __float_as_uint(BS(cur, k + 4, col));
            }
#pragma unroll
            for (int am = 0; am < 4; am++)
#pragma unroll
                for (int an = 0; an < 4; an++) {
                    asm volatile(
                        "mma.sync.aligned.m16n8k8.row.col.f32.tf32.tf32.f32 "
                        "{%0,%1,%2,%3}, {%4,%5,%6,%7}, {%8,%9}, {%0,%1,%2,%3};"
                        : "+f"(acc[am][an][0]), "+f"(acc[am][an][1]),
                          "+f"(acc[am][an][2]), "+f"(acc[am][an][3])
                        : "r"(af[am][0]), "r"(af[am][1]), "r"(af[am][2]), "r"(af[am][3]),
                          "r"(bf[an][0]), "r"(bf[an][1]));
                }
        }

        if (t + 1 < ntiles) {
            int nb = cur ^ 1;
#pragma unroll
            for (int r = 0; r < 4; r++) {
                AS(nb, arow + r * 32, acol + 0) = __uint_as_float(f2tf32(ar[r].x));
                AS(nb, arow + r * 32, acol + 1) = __uint_as_float(f2tf32(ar[r].y));
                AS(nb, arow + r * 32, acol + 2) = __uint_as_float(f2tf32(ar[r].z));
                AS(nb, arow + r * 32, acol + 3) = __uint_as_float(f2tf32(ar[r].w));
                BS(nb, brow + r * 8, bcol + 0) = __uint_as_float(f2tf32(br[r].x));
                BS(nb, brow + r * 8, bcol + 1) = __uint_as_float(f2tf32(br[r].y));
                BS(nb, brow + r * 8, bcol + 2) = __uint_as_float(f2tf32(br[r].z));
                BS(nb, brow + r * 8, bcol + 3) = __uint_as_float(f2tf32(br[r].w));
            }
        }
        __syncthreads();
    }

    // epilogue: bias + relu
#pragma unroll
    for (int am = 0; am < 4; am++) {
#pragma unroll
        for (int an = 0; an < 4; an++) {
            int row = m0 + wm * 64 + am * 16 + (lane >> 2);
            int col = n0 + wn * 32 + an * 8 + ((lane & 3) << 1);
            float b0 = bias[col], b1 = bias[col + 1];
            float v0 = fmaxf(acc[am][an][0] + b0, 0.0f);
            float v1 = fmaxf(acc[am][an][1] + b1, 0.0f);
            float v2 = fmaxf(acc[am][an][2] + b0, 0.0f);
            float v3 = fmaxf(acc[am][an][3] + b1, 0.0f);
            *(float2*)(C + (size_t)row * N + col) = make_float2(v0, v1);
            *(float2*)(C + (size_t)(row + 8) * N + col) = make_float2(v2, v3);
        }
    }
}

// ===========================================================================
// fp32 SGEMM 128x128x8 (unchanged from R1) — used for enc (N=768), res1 (N=1024)
// ===========================================================================
#define BM 128
#define BN 128
#define BK 8
#define TM 8
#define TN 8

template <int ACT>
__global__ __launch_bounds__(256, 2) void sgemm_k(
    const float* __restrict__ A, const float* __restrict__ W,
    const float* __restrict__ bias, const float* __restrict__ res,
    const float* __restrict__ pos, float* __restrict__ C,
    int M, int N, int K)
{
    __shared__ float As[BK][BM];
    __shared__ float Bs[BK][BN];

    int tid = threadIdx.x;
    int bm = blockIdx.y * BM;
    int bn = blockIdx.x * BN;
    int ty = tid >> 4, tx = tid & 15;
    int m0 = ty * TM, n0 = tx * TN;

    float acc[TM][TN] = {};

    int arow = tid >> 1;
    int acol = (tid & 1) * 4;
    int brow = tid >> 5;
    int bcol = (tid & 31) * 4;

    const float* Aptr = A + (size_t)(bm + arow) * K + acol;
    const float* Wptr = W + (size_t)brow * N + bn + bcol;

    for (int k0 = 0; k0 < K; k0 += BK) {
        float4 av = *(const float4*)(Aptr + k0);
        As[acol + 0][arow] = av.x;
        As[acol + 1][arow] = av.y;
        As[acol + 2][arow] = av.z;
        As[acol + 3][arow] = av.w;
        float4 bv = *(const float4*)(Wptr + (size_t)k0 * N);
        *(float4*)(&Bs[brow][bcol]) = bv;
        __syncthreads();

#pragma unroll
        for (int k = 0; k < BK; k++) {
            float a[TM], b[TN];
#pragma unroll
            for (int i = 0; i < TM; i++) a[i] = As[k][m0 + i];
#pragma unroll
            for (int j = 0; j < TN; j++) b[j] = Bs[k][n0 + j];
#pragma unroll
            for (int i = 0; i < TM; i++)
#pragma unroll
                for (int j = 0; j < TN; j++)
                    acc[i][j] = fmaf(a[i], b[j], acc[i][j]);
        }
        __syncthreads();
    }

#pragma unroll
    for (int i = 0; i < TM; i++) {
        int m = bm + m0 + i;
#pragma unroll
        for (int j = 0; j < TN; j++) {
            int n = bn + n0 + j;
            float v = acc[i][j] + bias[n];
            if (ACT == 1) v = fmaxf(v, 0.0f);
            else if (ACT == 2) v = tanhf(v);
            else if (ACT == 3) v = 0.5f * v * (1.0f + erff(v * 0.70710678118654752f));
            if (res) v += res[(size_t)m * N + n];
            if (pos) v += pos[(size_t)(m & 511) * N + n];
            C[(size_t)m * N + n] = v;
        }
    }
}

// ===========================================================================
// fp32 SGEMM 64x64x16, 128 threads — for small-N GEMMs (occupancy).
// ===========================================================================
template <int ACT>
__global__ __launch_bounds__(128) void sgemm64_k(
    const float* __restrict__ A, const float* __restrict__ W,
    const float* __restrict__ bias, const float* __restrict__ res,
    const float* __restrict__ pos, float* __restrict__ C,
    int M, int N, int K)
{
    __shared__ float As[16][64];
    __shared__ float Bs[16][64];

    int tid = threadIdx.x;
    int bm = blockIdx.y * 64;
    int bn = blockIdx.x * 64;
    int ty = tid >> 3, tx = tid & 7;   // 16 x 8
    int m0 = ty * 4, n0 = tx * 8;

    float acc[4][8] = {};

    int arow = tid >> 2;              // 0..31 (+32)
    int acol = (tid & 3) * 4;
    int brow = tid >> 4;              // 0..7 (+8)
    int bcol = (tid & 15) * 4;

    for (int k0 = 0; k0 < K; k0 += 16) {
#pragma unroll
        for (int r = 0; r < 2; r++) {
            float4 av = *(const float4*)(A + (size_t)(bm + arow + r * 32) * K + k0 + acol);
            As[acol + 0][arow + r * 32] = av.x;
            As[acol + 1][arow + r * 32] = av.y;
            As[acol + 2][arow + r * 32] = av.z;
            As[acol + 3][arow + r * 32] = av.w;
            float4 bv = *(const float4*)(W + (size_t)(k0 + brow + r * 8) * N + bn + bcol);
            *(float4*)(&Bs[brow + r * 8][bcol]) = bv;
        }
        __syncthreads();

#pragma unroll
        for (int k = 0; k < 16; k++) {
            float a[4], b[8];
#pragma unroll
            for (int i = 0; i < 4; i++) a[i] = As[k][m0 + i];
#pragma unroll
            for (int j = 0; j < 8; j++) b[j] = Bs[k][n0 + j];
#pragma unroll
            for (int i = 0; i < 4; i++)
#pragma unroll
                for (int j = 0; j < 8; j++)
                    acc[i][j] = fmaf(a[i], b[j], acc[i][j]);
        }
        __syncthreads();
    }

#pragma unroll
    for (int i = 0; i < 4; i++) {
        int m = bm + m0 + i;
#pragma unroll
        for (int j = 0; j < 8; j++) {
            int n = bn + n0 + j;
            float v = acc[i][j] + bias[n];
            if (ACT == 1) v = fmaxf(v, 0.0f);
            else if (ACT == 2) v = tanhf(v);
            else if (ACT == 3) v = 0.5f * v * (1.0f + erff(v * 0.70710678118654752f));
            if (res) v += res[(size_t)m * N + n];
            if (pos) v += pos[(size_t)(m & 511) * N + n];
            C[(size_t)m * N + n] = v;
        }
    }
}

// ===========================================================================
// LayerNorm (D=256), one block per row.
// ===========================================================================
__global__ void layernorm_k(const float* __restrict__ x, const float* __restrict__ g,
                            const float* __restrict__ b, float* __restrict__ y)
{
    int r = blockIdx.x, t = threadIdx.x;
    __shared__ float red[256];
    float v = x[(size_t)r * 256 + t];
    red[t] = v;
    __syncthreads();
    for (int s = 128; s > 0; s >>= 1) {
        if (t < s) red[t] += red[t + s];
        __syncthreads();
    }
    float mean = red[0] * (1.0f / 256.0f);
    __syncthreads();
    float d = v - mean;
    red[t] = d * d;
    __syncthreads();
    for (int s = 128; s > 0; s >>= 1) {
        if (t < s) red[t] += red[t + s];
        __syncthreads();
    }
    float var = red[0] * (1.0f / 256.0f);
    y[(size_t)r * 256 + t] = d * rsqrtf(var + 1e-5f) * g[t] + b[t];
}

// ===========================================================================
// Flash attention: block = (q-tile of 128, bh). 128 threads, 1 query/thread.
// Online softmax, K/V tiles in smem (row stride 36 floats for store banks).
// ===========================================================================
__global__ __launch_bounds__(128) void attn2_k(const float* __restrict__ c,
                                               float* __restrict__ x)
{
    const int S = 512, TD = 768;
    __shared__ float Ks[128][36];
    __shared__ float Vs[128][36];

    int qt  = blockIdx.x;           // 0..3
    int bh  = blockIdx.y;           // 0..63
    int b   = bh >> 3;
    int h   = bh & 7;
    int tid = threadIdx.x;
    int i   = qt * 128 + tid;       // this thread's query

    const float* base = c + (size_t)(b * S) * TD;
    const float scale = 0.17677669529663687f;   // 1/sqrt(32)

    float4 q[8];
    {
        const float4* qp = (const float4*)(base + (size_t)i * TD + h * 32);
#pragma unroll
        for (int d = 0; d < 8; d++) q[d] = qp[d];
    }

    float m = -1e30f, l = 0.0f;
    float4 acc[8];
#pragma unroll
    for (int d = 0; d < 8; d++) acc[d] = make_float4(0.f, 0.f, 0.f, 0.f);

    for (int kt = 0; kt <= qt; kt++) {
        int jbase = kt * 128;
        // cooperative load: thread tid loads K/V row jbase+tid
        {
            const float4* kp = (const float4*)(base + (size_t)(jbase + tid) * TD + 256 + h * 32);
            const float4* vp = (const float4*)(base + (size_t)(jbase + tid) * TD + 512 + h * 32);
            float4* kd = (float4*)&Ks[tid][0];
            float4* vd = (float4*)&Vs[tid][0];
#pragma unroll
            for (int d = 0; d < 8; d++) { kd[d] = kp[d]; vd[d] = vp[d]; }
        }
        __syncthreads();

        int jmax = (kt == qt) ? tid : 127;
        for (int jj = 0; jj <= jmax; jj++) {
            const float4* kr = (const float4*)&Ks[jj][0];
            float s = 0.0f;
#pragma unroll
            for (int d = 0; d < 8; d++) {
                float4 kv = kr[d];
                s = fmaf(q[d].x, kv.x, s);
                s = fmaf(q[d].y, kv.y, s);
                s = fmaf(q[d].z, kv.z, s);
                s = fmaf(q[d].w, kv.w, s);
            }
            s *= scale;
            const float4* vr = (const float4*)&Vs[jj][0];
            if (s <= m) {
                float p = __expf(s - m);
                l += p;
#pragma unroll
                for (int d = 0; d < 8; d++) {
                    float4 vv = vr[d];
                    acc[d].x = fmaf(p, vv.x, acc[d].x);
                    acc[d].y = fmaf(p, vv.y, acc[d].y);
                    acc[d].z = fmaf(p, vv.z, acc[d].z);
                    acc[d].w = fmaf(p, vv.w, acc[d].w);
                }
            } else {
                float corr = __expf(m - s);
                l = fmaf(l, corr, 1.0f);
#pragma unroll
                for (int d = 0; d < 8; d++) {
                    float4 vv = vr[d];
                    acc[d].x = fmaf(acc[d].x, corr, vv.x);
                    acc[d].y = fmaf(acc[d].y, corr, vv.y);
                    acc[d].z = fmaf(acc[d].z, corr, vv.z);
                    acc[d].w = fmaf(acc[d].w, corr, vv.w);
                }
                m = s;
            }
        }
        __syncthreads();
    }

    float inv = 1.0f / l;
    float4* xp = (float4*)(x + (size_t)(b * S + i) * 256 + h * 32);
#pragma unroll
    for (int d = 0; d < 8; d++) {
        float4 o = xp[d];
        o.x += acc[d].x * inv;
        o.y += acc[d].y * inv;
        o.z += acc[d].z * inv;
        o.w += acc[d].w * inv;
        xp[d] = o;
    }
}

// ===========================================================================
// Global standardization
// ===========================================================================
__global__ void zero_stats_k() { g_sum_d = 0.0; g_sumsq_d = 0.0; }

__global__ void stats_k(const float* __restrict__ e, int n)
{
    double s = 0.0, ss = 0.0;
    for (int i = blockIdx.x * blockDim.x + threadIdx.x; i < n;
         i += gridDim.x * blockDim.x) {
        double v = (double)e[i];
        s += v;
        ss += v * v;
    }
    for (int o = 16; o > 0; o >>= 1) {
        s  += __shfl_xor_sync(0xffffffffu, s, o);
        ss += __shfl_xor_sync(0xffffffffu, ss, o);
    }
    __shared__ double rs[8], rss[8];
    int w = threadIdx.x >> 5, lid = threadIdx.x & 31;
    if (lid == 0) { rs[w] = s; rss[w] = ss; }
    __syncthreads();
    if (threadIdx.x == 0) {
        double S = 0.0, SS = 0.0;
        int nw = blockDim.x >> 5;
        for (int i = 0; i < nw; i++) { S += rs[i]; SS += rss[i]; }
        atomicAdd(&g_sum_d, S);
        atomicAdd(&g_sumsq_d, SS);
    }
}

__global__ void normfinal_k(float* e, int n)
{
    double mean = g_sum_d / (double)n;
    double var = (g_sumsq_d - (double)n * mean * mean) / (double)(n - 1);
    double inv = rsqrt(var);
    for (int i = blockIdx.x * blockDim.x + threadIdx.x; i < n;
         i += gridDim.x * blockDim.x) {
        e[i] = (float)(((double)e[i] - mean) * inv + 1e-10);
    }
}

// ===========================================================================
extern "C" void kernel_launch(void* const* d_in, const int* in_sizes, int n_in,
                              void* d_out, int out_size)
{
    const float* state = (const float*)d_in[0];
    const float* fc1w = (const float*)d_in[1];
    const float* fc1b = (const float*)d_in[2];
    const float* fc2w = (const float*)d_in[3];
    const float* fc2b = (const float*)d_in[4];
    const float* fc3w = (const float*)d_in[5];
    const float* fc3b = (const float*)d_in[6];
    const float* fc4w = (const float*)d_in[7];
    const float* fc4b = (const float*)d_in[8];
    const float* fc5w = (const float*)d_in[9];
    const float* fc5b = (const float*)d_in[10];
    const float* prew = (const float*)d_in[11];
    const float* preb = (const float*)d_in[12];
    const float* posw = (const float*)d_in[13];
    const float* encw = (const float*)d_in[14];
    const float* encb = (const float*)d_in[15];
    const float* ln1g = (const float*)d_in[16];
    const float* ln1b = (const float*)d_in[17];
    const float* ln2g = (const float*)d_in[18];
    const float* ln2b = (const float*)d_in[19];
    const float* rw1  = (const float*)d_in[20];
    const float* rb1  = (const float*)d_in[21];
    const float* rw2  = (const float*)d_in[22];
    const float* rb2  = (const float*)d_in[23];
    const float* outw = (const float*)d_in[24];
    const float* outb = (const float*)d_in[25];
    float* out = (float*)d_out;

    float *ga, *gb, *gx, *gxn, *gc, *gh;
    cudaGetSymbolAddress((void**)&ga,  g_a);
    cudaGetSymbolAddress((void**)&gb,  g_b);
    cudaGetSymbolAddress((void**)&gx,  g_x);
    cudaGetSymbolAddress((void**)&gxn, g_xn);
    cudaGetSymbolAddress((void**)&gc,  g_c);
    cudaGetSymbolAddress((void**)&gh,  g_h);

    const int M = 4096;
    const int TG_SMEM = (2 * 128 * 36 + 2 * 32 * 136) * 4;  // 71680 B
    static int smem_set = 0;
    if (!smem_set) {
        cudaFuncSetAttribute(tgemm_relu_k,
                             cudaFuncAttributeMaxDynamicSharedMemorySize, TG_SMEM);
        smem_set = 1;
    }

    // MLP funnel: fc1-fc4 on tensor cores (tf32), fc5 fp32+tanh
    tgemm_relu_k<<<dim3(32, 32), 256, TG_SMEM>>>(state, fc1w, fc1b, ga, M, 4096, 4096);
    tgemm_relu_k<<<dim3(16, 32), 256, TG_SMEM>>>(ga, fc2w, fc2b, gb, M, 2048, 4096);
    tgemm_relu_k<<<dim3(8, 32), 256, TG_SMEM>>>(gb, fc3w, fc3b, ga, M, 1024, 2048);
    tgemm_relu_k<<<dim3(4, 32), 256, TG_SMEM>>>(ga, fc4w, fc4b, gb, M, 512, 1024);
    sgemm64_k<2><<<dim3(4, 64), 128>>>(gb, fc5w, fc5b, nullptr, nullptr, ga, M, 256, 512);
    sgemm64_k<0><<<dim3(4, 64), 128>>>(ga, prew, preb, nullptr, posw, gx, M, 256, 256);

    for (int l = 0; l < 8; l++) {
        layernorm_k<<<4096, 256>>>(gx, ln1g + l * 256, ln1b + l * 256, gxn);
        sgemm_k<0><<<dim3(6, 32), 256>>>(gxn, encw + (size_t)l * 256 * 768,
                                         encb + l * 768, nullptr, nullptr, gc, M, 768, 256);
        attn2_k<<<dim3(4, 64), 128>>>(gc, gx);
        layernorm_k<<<4096, 256>>>(gx, ln2g + l * 256, ln2b + l * 256, gx);
        sgemm_k<3><<<dim3(8, 32), 256>>>(gx, rw1 + (size_t)l * 256 * 1024,
                                         rb1 + l * 1024, nullptr, nullptr, gh, M, 1024, 256);
        sgemm64_k<0><<<dim3(4, 64), 128>>>(gh, rw2 + (size_t)l * 1024 * 256,
                                           rb2 + l * 256, gx, nullptr, gx, M, 256, 1024);
    }

    sgemm64_k<0><<<dim3(2, 64), 128>>>(gx, outw, outb, nullptr, nullptr, out, M, 128, 256);
    zero_stats_k<<<1, 1>>>();
    stats_k<<<512, 256>>>(out, 4096 * 128);
    normfinal_k<<<512, 256>>>(out, 4096 * 128);
}

// round 4
// speedup vs baseline: 7.8168x; 1.6219x over previous
#include <cuda_runtime.h>
#include <math.h>
#include <stdint.h>

// ---------------------------------------------------------------------------
// AttentionEncoderModel on GB300 — R4.
// tf32 mma GEMMs with cp.async pipeline + RNA rounding at register load.
// Final out-projection in fp32 for precision margin.
// ---------------------------------------------------------------------------

__device__ float g_a[4096 * 4096];
__device__ float g_b[4096 * 2048];
__device__ float g_x[4096 * 256];
__device__ float g_xn[4096 * 256];
__device__ float g_c[4096 * 768];
__device__ float g_h[4096 * 1024];
__device__ double g_sum_d, g_sumsq_d;

#define CP16(dst, src) \
    asm volatile("cp.async.ca.shared.global [%0], [%1], 16;" :: "r"(dst), "l"(src))

__device__ __forceinline__ uint32_t f2tf32(float f) {
    uint32_t u;
    asm("cvt.rna.tf32.f32 %0, %1;" : "=r"(u) : "f"(f));
    return u;
}

// ===========================================================================
// tf32 tensor-core GEMM. Tiles BMT x 128 x 32, 256 threads (8 warps, 2x4),
// warp tile (BMT/2) x 32, mma m16n8k8, cp.async double buffering.
// RNA tf32 conversion applied in registers right before mma (unbiased).
// ACT: 0=none 1=relu 2=tanh 3=gelu(exact)
// ===========================================================================
template <int BMT, int ACT, bool HASRES, bool HASPOS>
__global__ __launch_bounds__(256, (BMT == 128) ? 2 : 3)
void tgemm_k(const float* __restrict__ A, const float* __restrict__ W,
             const float* __restrict__ bias, const float* __restrict__ res,
             const float* __restrict__ pos, float* __restrict__ C,
             int M, int N, int K)
{
    constexpr int AM = BMT / 32;
    extern __shared__ float dynsmem[];
    float* As_ = dynsmem;                   // [2][BMT][36]
    float* Bs_ = dynsmem + 2 * BMT * 36;    // [2][32][136]

    const int tid = threadIdx.x;
    const int lane = tid & 31, wid = tid >> 5;
    const int wm = wid >> 2, wn = wid & 3;
    const int m0 = blockIdx.y * BMT, n0 = blockIdx.x * 128;

    float acc[AM][4][4] = {};

    const int arow = tid >> 3, acol = (tid & 7) * 4;
    const int brow = tid >> 5, bcol = (tid & 31) * 4;

    const uint32_t sA = (uint32_t)__cvta_generic_to_shared(As_);
    const uint32_t sB = (uint32_t)__cvta_generic_to_shared(Bs_);

    const int ntiles = K >> 5;

    auto issue = [&](int t, int buf) {
        int kbase = t * 32;
#pragma unroll
        for (int r = 0; r < AM; r++) {
            uint32_t d = sA + (uint32_t)(((buf * BMT) + arow + r * 32) * 36 + acol) * 4u;
            const float* s = A + (size_t)(m0 + arow + r * 32) * K + kbase + acol;
            CP16(d, s);
        }
#pragma unroll
        for (int r = 0; r < 4; r++) {
            uint32_t d = sB + (uint32_t)(((buf * 32) + brow + r * 8) * 136 + bcol) * 4u;
            const float* s = W + (size_t)(kbase + brow + r * 8) * N + n0 + bcol;
            CP16(d, s);
        }
        asm volatile("cp.async.commit_group;");
    };

    issue(0, 0);

    for (int t = 0; t < ntiles; t++) {
        int cur = t & 1;
        asm volatile("cp.async.wait_group 0;");
        __syncthreads();
        if (t + 1 < ntiles) issue(t + 1, cur ^ 1);

        const float* Ab = As_ + (size_t)cur * BMT * 36;
        const float* Bb = Bs_ + (size_t)cur * 32 * 136;

#pragma unroll
        for (int ks = 0; ks < 4; ks++) {
            int kk = ks * 8;
            uint32_t af[AM][4], bf[4][2];
#pragma unroll
            for (int am = 0; am < AM; am++) {
                int row = wm * (BMT / 2) + am * 16 + (lane >> 2);
                int k = kk + (lane & 3);
                af[am][0] = f2tf32(Ab[row * 36 + k]);
                af[am][1] = f2tf32(Ab[(row + 8) * 36 + k]);
                af[am][2] = f2tf32(Ab[row * 36 + k + 4]);
                af[am][3] = f2tf32(Ab[(row + 8) * 36 + k + 4]);
            }
#pragma unroll
            for (int an = 0; an < 4; an++) {
                int col = wn * 32 + an * 8 + (lane >> 2);
                int k = kk + (lane & 3);
                bf[an][0] = f2tf32(Bb[k * 136 + col]);
                bf[an][1] = f2tf32(Bb[(k + 4) * 136 + col]);
            }
#pragma unroll
            for (int am = 0; am < AM; am++)
#pragma unroll
                for (int an = 0; an < 4; an++) {
                    asm volatile(
                        "mma.sync.aligned.m16n8k8.row.col.f32.tf32.tf32.f32 "
                        "{%0,%1,%2,%3}, {%4,%5,%6,%7}, {%8,%9}, {%0,%1,%2,%3};"
                        : "+f"(acc[am][an][0]), "+f"(acc[am][an][1]),
                          "+f"(acc[am][an][2]), "+f"(acc[am][an][3])
                        : "r"(af[am][0]), "r"(af[am][1]), "r"(af[am][2]), "r"(af[am][3]),
                          "r"(bf[an][0]), "r"(bf[an][1]));
                }
        }
        __syncthreads();
    }

#pragma unroll
    for (int am = 0; am < AM; am++) {
#pragma unroll
        for (int an = 0; an < 4; an++) {
            int row = m0 + wm * (BMT / 2) + am * 16 + (lane >> 2);
            int col = n0 + wn * 32 + an * 8 + ((lane & 3) << 1);
            float b0 = bias[col], b1 = bias[col + 1];
#pragma unroll
            for (int h = 0; h < 2; h++) {
                int m = row + h * 8;
                float v0 = acc[am][an][h * 2 + 0] + b0;
                float v1 = acc[am][an][h * 2 + 1] + b1;
                if (ACT == 1) { v0 = fmaxf(v0, 0.f); v1 = fmaxf(v1, 0.f); }
                else if (ACT == 2) { v0 = tanhf(v0); v1 = tanhf(v1); }
                else if (ACT == 3) {
                    v0 = 0.5f * v0 * (1.0f + erff(v0 * 0.70710678118654752f));
                    v1 = 0.5f * v1 * (1.0f + erff(v1 * 0.70710678118654752f));
                }
                if (HASRES) {
                    float2 rr = *(const float2*)(res + (size_t)m * N + col);
                    v0 += rr.x; v1 += rr.y;
                }
                if (HASPOS) {
                    float2 pp = *(const float2*)(pos + (size_t)(m & 511) * N + col);
                    v0 += pp.x; v1 += pp.y;
                }
                *(float2*)(C + (size_t)m * N + col) = make_float2(v0, v1);
            }
        }
    }
}

// ===========================================================================
// fp32 SGEMM 64x64x16, 128 threads — final out projection (precision margin).
// ===========================================================================
__global__ __launch_bounds__(128) void sgemm64_k(
    const float* __restrict__ A, const float* __restrict__ W,
    const float* __restrict__ bias, float* __restrict__ C,
    int M, int N, int K)
{
    __shared__ float As[16][64];
    __shared__ float Bs[16][64];

    int tid = threadIdx.x;
    int bm = blockIdx.y * 64;
    int bn = blockIdx.x * 64;
    int ty = tid >> 3, tx = tid & 7;
    int m0 = ty * 4, n0 = tx * 8;

    float acc[4][8] = {};

    int arow = tid >> 2, acol = (tid & 3) * 4;
    int brow = tid >> 4, bcol = (tid & 15) * 4;

    for (int k0 = 0; k0 < K; k0 += 16) {
#pragma unroll
        for (int r = 0; r < 2; r++) {
            float4 av = *(const float4*)(A + (size_t)(bm + arow + r * 32) * K + k0 + acol);
            As[acol + 0][arow + r * 32] = av.x;
            As[acol + 1][arow + r * 32] = av.y;
            As[acol + 2][arow + r * 32] = av.z;
            As[acol + 3][arow + r * 32] = av.w;
            float4 bv = *(const float4*)(W + (size_t)(k0 + brow + r * 8) * N + bn + bcol);
            *(float4*)(&Bs[brow + r * 8][bcol]) = bv;
        }
        __syncthreads();

#pragma unroll
        for (int k = 0; k < 16; k++) {
            float a[4], b[8];
#pragma unroll
            for (int i = 0; i < 4; i++) a[i] = As[k][m0 + i];
#pragma unroll
            for (int j = 0; j < 8; j++) b[j] = Bs[k][n0 + j];
#pragma unroll
            for (int i = 0; i < 4; i++)
#pragma unroll
                for (int j = 0; j < 8; j++)
                    acc[i][j] = fmaf(a[i], b[j], acc[i][j]);
        }
        __syncthreads();
    }

#pragma unroll
    for (int i = 0; i < 4; i++) {
        int m = bm + m0 + i;
#pragma unroll
        for (int j = 0; j < 8; j++) {
            int n = bn + n0 + j;
            C[(size_t)m * N + n] = acc[i][j] + bias[n];
        }
    }
}

// ===========================================================================
// LayerNorm D=256: one warp per row, 8 rows/block, shuffle-only.
// ===========================================================================
__global__ __launch_bounds__(256) void layernorm8_k(
    const float* __restrict__ x, const float* __restrict__ g,
    const float* __restrict__ b, float* __restrict__ y)
{
    int w = threadIdx.x >> 5, lane = threadIdx.x & 31;
    size_t r = (size_t)blockIdx.x * 8 + w;
    const float4* xp = (const float4*)(x + r * 256);
    float4 v0 = xp[lane];
    float4 v1 = xp[lane + 32];

    float s = v0.x + v0.y + v0.z + v0.w + v1.x + v1.y + v1.z + v1.w;
#pragma unroll
    for (int o = 16; o > 0; o >>= 1) s += __shfl_xor_sync(0xffffffffu, s, o);
    float mean = s * (1.0f / 256.0f);

    float d0x = v0.x - mean, d0y = v0.y - mean, d0z = v0.z - mean, d0w = v0.w - mean;
    float d1x = v1.x - mean, d1y = v1.y - mean, d1z = v1.z - mean, d1w = v1.w - mean;
    float ss = d0x * d0x + d0y * d0y + d0z * d0z + d0w * d0w
             + d1x * d1x + d1y * d1y + d1z * d1z + d1w * d1w;
#pragma unroll
    for (int o = 16; o > 0; o >>= 1) ss += __shfl_xor_sync(0xffffffffu, ss, o);
    float inv = rsqrtf(ss * (1.0f / 256.0f) + 1e-5f);

    float4 g0 = ((const float4*)g)[lane], g1 = ((const float4*)g)[lane + 32];
    float4 b0 = ((const float4*)b)[lane], b1 = ((const float4*)b)[lane + 32];
    float4* yp = (float4*)(y + r * 256);
    yp[lane] = make_float4(d0x * inv * g0.x + b0.x, d0y * inv * g0.y + b0.y,
                           d0z * inv * g0.z + b0.z, d0w * inv * g0.w + b0.w);
    yp[lane + 32] = make_float4(d1x * inv * g1.x + b1.x, d1y * inv * g1.y + b1.y,
                                d1z * inv * g1.z + b1.z, d1w * inv * g1.w + b1.w);
}

// ===========================================================================
// Flash attention
// ===========================================================================
__global__ __launch_bounds__(128) void attn2_k(const float* __restrict__ c,
                                               float* __restrict__ x)
{
    const int S = 512, TD = 768;
    __shared__ float Ks[128][36];
    __shared__ float Vs[128][36];

    int qt  = blockIdx.x;
    int bh  = blockIdx.y;
    int b   = bh >> 3;
    int h   = bh & 7;
    int tid = threadIdx.x;
    int i   = qt * 128 + tid;

    const float* base = c + (size_t)(b * S) * TD;
    const float scale = 0.17677669529663687f;

    float4 q[8];
    {
        const float4* qp = (const float4*)(base + (size_t)i * TD + h * 32);
#pragma unroll
        for (int d = 0; d < 8; d++) q[d] = qp[d];
    }

    float m = -1e30f, l = 0.0f;
    float4 acc[8];
#pragma unroll
    for (int d = 0; d < 8; d++) acc[d] = make_float4(0.f, 0.f, 0.f, 0.f);

    for (int kt = 0; kt <= qt; kt++) {
        int jbase = kt * 128;
        {
            const float4* kp = (const float4*)(base + (size_t)(jbase + tid) * TD + 256 + h * 32);
            const float4* vp = (const float4*)(base + (size_t)(jbase + tid) * TD + 512 + h * 32);
            float4* kd = (float4*)&Ks[tid][0];
            float4* vd = (float4*)&Vs[tid][0];
#pragma unroll
            for (int d = 0; d < 8; d++) { kd[d] = kp[d]; vd[d] = vp[d]; }
        }
        __syncthreads();

        int jmax = (kt == qt) ? tid : 127;
        for (int jj = 0; jj <= jmax; jj++) {
            const float4* kr = (const float4*)&Ks[jj][0];
            float s = 0.0f;
#pragma unroll
            for (int d = 0; d < 8; d++) {
                float4 kv = kr[d];
                s = fmaf(q[d].x, kv.x, s);
                s = fmaf(q[d].y, kv.y, s);
                s = fmaf(q[d].z, kv.z, s);
                s = fmaf(q[d].w, kv.w, s);
            }
            s *= scale;
            const float4* vr = (const float4*)&Vs[jj][0];
            if (s <= m) {
                float p = __expf(s - m);
                l += p;
#pragma unroll
                for (int d = 0; d < 8; d++) {
                    float4 vv = vr[d];
                    acc[d].x = fmaf(p, vv.x, acc[d].x);
                    acc[d].y = fmaf(p, vv.y, acc[d].y);
                    acc[d].z = fmaf(p, vv.z, acc[d].z);
                    acc[d].w = fmaf(p, vv.w, acc[d].w);
                }
            } else {
                float corr = __expf(m - s);
                l = fmaf(l, corr, 1.0f);
#pragma unroll
                for (int d = 0; d < 8; d++) {
                    float4 vv = vr[d];
                    acc[d].x = fmaf(acc[d].x, corr, vv.x);
                    acc[d].y = fmaf(acc[d].y, corr, vv.y);
                    acc[d].z = fmaf(acc[d].z, corr, vv.z);
                    acc[d].w = fmaf(acc[d].w, corr, vv.w);
                }
                m = s;
            }
        }
        __syncthreads();
    }

    float inv = 1.0f / l;
    float4* xp = (float4*)(x + (size_t)(b * S + i) * 256 + h * 32);
#pragma unroll
    for (int d = 0; d < 8; d++) {
        float4 o = xp[d];
        o.x += acc[d].x * inv;
        o.y += acc[d].y * inv;
        o.z += acc[d].z * inv;
        o.w += acc[d].w * inv;
        xp[d] = o;
    }
}

// ===========================================================================
// Global standardization
// ===========================================================================
__global__ void zero_stats_k() { g_sum_d = 0.0; g_sumsq_d = 0.0; }

__global__ void stats_k(const float* __restrict__ e, int n)
{
    double s = 0.0, ss = 0.0;
    for (int i = blockIdx.x * blockDim.x + threadIdx.x; i < n;
         i += gridDim.x * blockDim.x) {
        double v = (double)e[i];
        s += v;
        ss += v * v;
    }
    for (int o = 16; o > 0; o >>= 1) {
        s  += __shfl_xor_sync(0xffffffffu, s, o);
        ss += __shfl_xor_sync(0xffffffffu, ss, o);
    }
    __shared__ double rs[8], rss[8];
    int w = threadIdx.x >> 5, lid = threadIdx.x & 31;
    if (lid == 0) { rs[w] = s; rss[w] = ss; }
    __syncthreads();
    if (threadIdx.x == 0) {
        double S = 0.0, SS = 0.0;
        int nw = blockDim.x >> 5;
        for (int i = 0; i < nw; i++) { S += rs[i]; SS += rss[i]; }
        atomicAdd(&g_sum_d, S);
        atomicAdd(&g_sumsq_d, SS);
    }
}

__global__ void normfinal_k(float* e, int n)
{
    double mean = g_sum_d / (double)n;
    double var = (g_sumsq_d - (double)n * mean * mean) / (double)(n - 1);
    double inv = rsqrt(var);
    for (int i = blockIdx.x * blockDim.x + threadIdx.x; i < n;
         i += gridDim.x * blockDim.x) {
        e[i] = (float)(((double)e[i] - mean) * inv + 1e-10);
    }
}

// ===========================================================================
extern "C" void kernel_launch(void* const* d_in, const int* in_sizes, int n_in,
                              void* d_out, int out_size)
{
    const float* state = (const float*)d_in[0];
    const float* fc1w = (const float*)d_in[1];
    const float* fc1b = (const float*)d_in[2];
    const float* fc2w = (const float*)d_in[3];
    const float* fc2b = (const float*)d_in[4];
    const float* fc3w = (const float*)d_in[5];
    const float* fc3b = (const float*)d_in[6];
    const float* fc4w = (const float*)d_in[7];
    const float* fc4b = (const float*)d_in[8];
    const float* fc5w = (const float*)d_in[9];
    const float* fc5b = (const float*)d_in[10];
    const float* prew = (const float*)d_in[11];
    const float* preb = (const float*)d_in[12];
    const float* posw = (const float*)d_in[13];
    const float* encw = (const float*)d_in[14];
    const float* encb = (const float*)d_in[15];
    const float* ln1g = (const float*)d_in[16];
    const float* ln1b = (const float*)d_in[17];
    const float* ln2g = (const float*)d_in[18];
    const float* ln2b = (const float*)d_in[19];
    const float* rw1  = (const float*)d_in[20];
    const float* rb1  = (const float*)d_in[21];
    const float* rw2  = (const float*)d_in[22];
    const float* rb2  = (const float*)d_in[23];
    const float* outw = (const float*)d_in[24];
    const float* outb = (const float*)d_in[25];
    float* out = (float*)d_out;

    float *ga, *gb, *gx, *gxn, *gc, *gh;
    cudaGetSymbolAddress((void**)&ga,  g_a);
    cudaGetSymbolAddress((void**)&gb,  g_b);
    cudaGetSymbolAddress((void**)&gx,  g_x);
    cudaGetSymbolAddress((void**)&gxn, g_xn);
    cudaGetSymbolAddress((void**)&gc,  g_c);
    cudaGetSymbolAddress((void**)&gh,  g_h);

    const int M = 4096;
    const int SM128 = (2 * 128 * 36 + 2 * 32 * 136) * 4;  // 71680
    const int SM64  = (2 * 64  * 36 + 2 * 32 * 136) * 4;  // 53248

    cudaFuncSetAttribute(tgemm_k<128,1,false,false>, cudaFuncAttributeMaxDynamicSharedMemorySize, SM128);
    cudaFuncSetAttribute(tgemm_k<128,0,false,false>, cudaFuncAttributeMaxDynamicSharedMemorySize, SM128);
    cudaFuncSetAttribute(tgemm_k<128,3,false,false>, cudaFuncAttributeMaxDynamicSharedMemorySize, SM128);
    cudaFuncSetAttribute(tgemm_k<64,2,false,false>,  cudaFuncAttributeMaxDynamicSharedMemorySize, SM64);
    cudaFuncSetAttribute(tgemm_k<64,0,false,true>,   cudaFuncAttributeMaxDynamicSharedMemorySize, SM64);
    cudaFuncSetAttribute(tgemm_k<64,0,true,false>,   cudaFuncAttributeMaxDynamicSharedMemorySize, SM64);

    // MLP funnel
    tgemm_k<128,1,false,false><<<dim3(32, 32), 256, SM128>>>(state, fc1w, fc1b, nullptr, nullptr, ga, M, 4096, 4096);
    tgemm_k<128,1,false,false><<<dim3(16, 32), 256, SM128>>>(ga, fc2w, fc2b, nullptr, nullptr, gb, M, 2048, 4096);
    tgemm_k<128,1,false,false><<<dim3(8, 32), 256, SM128>>>(gb, fc3w, fc3b, nullptr, nullptr, ga, M, 1024, 2048);
    tgemm_k<128,1,false,false><<<dim3(4, 32), 256, SM128>>>(ga, fc4w, fc4b, nullptr, nullptr, gb, M, 512, 1024);
    tgemm_k<64,2,false,false><<<dim3(2, 64), 256, SM64>>>(gb, fc5w, fc5b, nullptr, nullptr, ga, M, 256, 512);
    tgemm_k<64,0,false,true><<<dim3(2, 64), 256, SM64>>>(ga, prew, preb, nullptr, posw, gx, M, 256, 256);

    for (int l = 0; l < 8; l++) {
        layernorm8_k<<<512, 256>>>(gx, ln1g + l * 256, ln1b + l * 256, gxn);
        tgemm_k<128,0,false,false><<<dim3(6, 32), 256, SM128>>>(gxn, encw + (size_t)l * 256 * 768,
                                                                encb + l * 768, nullptr, nullptr, gc, M, 768, 256);
        attn2_k<<<dim3(4, 64), 128>>>(gc, gx);
        layernorm8_k<<<512, 256>>>(gx, ln2g + l * 256, ln2b + l * 256, gx);
        tgemm_k<128,3,false,false><<<dim3(8, 32), 256, SM128>>>(gx, rw1 + (size_t)l * 256 * 1024,
                                                                rb1 + l * 1024, nullptr, nullptr, gh, M, 1024, 256);
        tgemm_k<64,0,true,false><<<dim3(2, 64), 256, SM64>>>(gh, rw2 + (size_t)l * 1024 * 256,
                                                             rb2 + l * 256, gx, nullptr, gx, M, 256, 1024);
    }

    // final projection in fp32 (precision margin), then global standardize
    sgemm64_k<<<dim3(2, 64), 128>>>(gx, outw, outb, out, M, 128, 256);
    zero_stats_k<<<1, 1>>>();
    stats_k<<<512, 256>>>(out, 4096 * 128);
    normfinal_k<<<512, 256>>>(out, 4096 * 128);
}

// round 5
// speedup vs baseline: 7.8769x; 1.0077x over previous
#include <cuda_runtime.h>
#include <math.h>
#include <stdint.h>

// ---------------------------------------------------------------------------
// AttentionEncoderModel on GB300 — R5.
// tf32 mma GEMMs (RNA rounding in registers), cp.async 2-stage pipeline.
// R5: every GEMM launch sized for >=2 CTAs/SM (grid >= 256); new 128-thread
// 64x64 kernel for small-N GEMMs; BMT=64 variant now targets 2 CTAs (128 regs).
// ---------------------------------------------------------------------------

__device__ float g_a[4096 * 4096];
__device__ float g_b[4096 * 2048];
__device__ float g_x[4096 * 256];
__device__ float g_xn[4096 * 256];
__device__ float g_c[4096 * 768];
__device__ float g_h[4096 * 1024];
__device__ double g_sum_d, g_sumsq_d;

#define CP16(dst, src) \
    asm volatile("cp.async.ca.shared.global [%0], [%1], 16;" :: "r"(dst), "l"(src))

__device__ __forceinline__ uint32_t f2tf32(float f) {
    uint32_t u;
    asm("cvt.rna.tf32.f32 %0, %1;" : "=r"(u) : "f"(f));
    return u;
}

#define MMA_TF32(acc, a0, a1, a2, a3, b0, b1) \
    asm volatile( \
        "mma.sync.aligned.m16n8k8.row.col.f32.tf32.tf32.f32 " \
        "{%0,%1,%2,%3}, {%4,%5,%6,%7}, {%8,%9}, {%0,%1,%2,%3};" \
        : "+f"((acc)[0]), "+f"((acc)[1]), "+f"((acc)[2]), "+f"((acc)[3]) \
        : "r"(a0), "r"(a1), "r"(a2), "r"(a3), "r"(b0), "r"(b1))

__device__ __forceinline__ float apply_act(float v, int ACT) {
    if (ACT == 1) return fmaxf(v, 0.0f);
    if (ACT == 2) return tanhf(v);
    if (ACT == 3) return 0.5f * v * (1.0f + erff(v * 0.70710678118654752f));
    return v;
}

// ===========================================================================
// tf32 GEMM, tiles BMT x 128 x 32, 256 threads (8 warps, (BMT/64) x ...).
// ===========================================================================
template <int BMT, int ACT, bool HASRES, bool HASPOS>
__global__ __launch_bounds__(256, 2)
void tgemm_k(const float* __restrict__ A, const float* __restrict__ W,
             const float* __restrict__ bias, const float* __restrict__ res,
             const float* __restrict__ pos, float* __restrict__ C,
             int M, int N, int K)
{
    constexpr int AM = BMT / 32;
    extern __shared__ float dynsmem[];
    float* As_ = dynsmem;                   // [2][BMT][36]
    float* Bs_ = dynsmem + 2 * BMT * 36;    // [2][32][136]

    const int tid = threadIdx.x;
    const int lane = tid & 31, wid = tid >> 5;
    const int wm = wid >> 2, wn = wid & 3;
    const int m0 = blockIdx.y * BMT, n0 = blockIdx.x * 128;

    float acc[AM][4][4] = {};

    const int arow = tid >> 3, acol = (tid & 7) * 4;
    const int brow = tid >> 5, bcol = (tid & 31) * 4;

    const uint32_t sA = (uint32_t)__cvta_generic_to_shared(As_);
    const uint32_t sB = (uint32_t)__cvta_generic_to_shared(Bs_);

    const int ntiles = K >> 5;

    auto issue = [&](int t, int buf) {
        int kbase = t * 32;
#pragma unroll
        for (int r = 0; r < AM; r++) {
            uint32_t d = sA + (uint32_t)(((buf * BMT) + arow + r * 32) * 36 + acol) * 4u;
            const float* s = A + (size_t)(m0 + arow + r * 32) * K + kbase + acol;
            CP16(d, s);
        }
#pragma unroll
        for (int r = 0; r < 4; r++) {
            uint32_t d = sB + (uint32_t)(((buf * 32) + brow + r * 8) * 136 + bcol) * 4u;
            const float* s = W + (size_t)(kbase + brow + r * 8) * N + n0 + bcol;
            CP16(d, s);
        }
        asm volatile("cp.async.commit_group;");
    };

    issue(0, 0);

    for (int t = 0; t < ntiles; t++) {
        int cur = t & 1;
        asm volatile("cp.async.wait_group 0;");
        __syncthreads();
        if (t + 1 < ntiles) issue(t + 1, cur ^ 1);

        const float* Ab = As_ + (size_t)cur * BMT * 36;
        const float* Bb = Bs_ + (size_t)cur * 32 * 136;

#pragma unroll
        for (int ks = 0; ks < 4; ks++) {
            int kk = ks * 8;
            uint32_t af[AM][4], bf[4][2];
#pragma unroll
            for (int am = 0; am < AM; am++) {
                int row = wm * (BMT / 2) + am * 16 + (lane >> 2);
                int k = kk + (lane & 3);
                af[am][0] = f2tf32(Ab[row * 36 + k]);
                af[am][1] = f2tf32(Ab[(row + 8) * 36 + k]);
                af[am][2] = f2tf32(Ab[row * 36 + k + 4]);
                af[am][3] = f2tf32(Ab[(row + 8) * 36 + k + 4]);
            }
#pragma unroll
            for (int an = 0; an < 4; an++) {
                int col = wn * 32 + an * 8 + (lane >> 2);
                int k = kk + (lane & 3);
                bf[an][0] = f2tf32(Bb[k * 136 + col]);
                bf[an][1] = f2tf32(Bb[(k + 4) * 136 + col]);
            }
#pragma unroll
            for (int am = 0; am < AM; am++)
#pragma unroll
                for (int an = 0; an < 4; an++)
                    MMA_TF32(acc[am][an], af[am][0], af[am][1], af[am][2], af[am][3],
                             bf[an][0], bf[an][1]);
        }
        __syncthreads();
    }

#pragma unroll
    for (int am = 0; am < AM; am++) {
#pragma unroll
        for (int an = 0; an < 4; an++) {
            int row = m0 + wm * (BMT / 2) + am * 16 + (lane >> 2);
            int col = n0 + wn * 32 + an * 8 + ((lane & 3) << 1);
            float b0 = bias[col], b1 = bias[col + 1];
#pragma unroll
            for (int h = 0; h < 2; h++) {
                int m = row + h * 8;
                float v0 = apply_act(acc[am][an][h * 2 + 0] + b0, ACT);
                float v1 = apply_act(acc[am][an][h * 2 + 1] + b1, ACT);
                if (HASRES) {
                    float2 rr = *(const float2*)(res + (size_t)m * N + col);
                    v0 += rr.x; v1 += rr.y;
                }
                if (HASPOS) {
                    float2 pp = *(const float2*)(pos + (size_t)(m & 511) * N + col);
                    v0 += pp.x; v1 += pp.y;
                }
                *(float2*)(C + (size_t)m * N + col) = make_float2(v0, v1);
            }
        }
    }
}

// ===========================================================================
// tf32 GEMM small: tiles 64 x 64 x 32, 128 threads (4 warps 2x2, 32x32 each).
// ===========================================================================
template <int ACT, bool HASRES, bool HASPOS>
__global__ __launch_bounds__(128, 4)
void tgemm_s(const float* __restrict__ A, const float* __restrict__ W,
             const float* __restrict__ bias, const float* __restrict__ res,
             const float* __restrict__ pos, float* __restrict__ C,
             int M, int N, int K)
{
    extern __shared__ float dynsmem[];
    float* As_ = dynsmem;                  // [2][64][36]
    float* Bs_ = dynsmem + 2 * 64 * 36;    // [2][32][72]

    const int tid = threadIdx.x;
    const int lane = tid & 31, wid = tid >> 5;
    const int wm = wid >> 1, wn = wid & 1;
    const int m0 = blockIdx.y * 64, n0 = blockIdx.x * 64;

    float acc[2][4][4] = {};

    const int arow = tid >> 3, acol = (tid & 7) * 4;   // 16 rows x 8 slots
    const int brow = tid >> 4, bcol = (tid & 15) * 4;  // 8 rows x 16 slots

    const uint32_t sA = (uint32_t)__cvta_generic_to_shared(As_);
    const uint32_t sB = (uint32_t)__cvta_generic_to_shared(Bs_);

    const int ntiles = K >> 5;

    auto issue = [&](int t, int buf) {
        int kbase = t * 32;
#pragma unroll
        for (int r = 0; r < 4; r++) {
            uint32_t d = sA + (uint32_t)(((buf * 64) + arow + r * 16) * 36 + acol) * 4u;
            const float* s = A + (size_t)(m0 + arow + r * 16) * K + kbase + acol;
            CP16(d, s);
        }
#pragma unroll
        for (int r = 0; r < 4; r++) {
            uint32_t d = sB + (uint32_t)(((buf * 32) + brow + r * 8) * 72 + bcol) * 4u;
            const float* s = W + (size_t)(kbase + brow + r * 8) * N + n0 + bcol;
            CP16(d, s);
        }
        asm volatile("cp.async.commit_group;");
    };

    issue(0, 0);

    for (int t = 0; t < ntiles; t++) {
        int cur = t & 1;
        asm volatile("cp.async.wait_group 0;");
        __syncthreads();
        if (t + 1 < ntiles) issue(t + 1, cur ^ 1);

        const float* Ab = As_ + (size_t)cur * 64 * 36;
        const float* Bb = Bs_ + (size_t)cur * 32 * 72;

#pragma unroll
        for (int ks = 0; ks < 4; ks++) {
            int kk = ks * 8;
            uint32_t af[2][4], bf[4][2];
#pragma unroll
            for (int am = 0; am < 2; am++) {
                int row = wm * 32 + am * 16 + (lane >> 2);
                int k = kk + (lane & 3);
                af[am][0] = f2tf32(Ab[row * 36 + k]);
                af[am][1] = f2tf32(Ab[(row + 8) * 36 + k]);
                af[am][2] = f2tf32(Ab[row * 36 + k + 4]);
                af[am][3] = f2tf32(Ab[(row + 8) * 36 + k + 4]);
            }
#pragma unroll
            for (int an = 0; an < 4; an++) {
                int col = wn * 32 + an * 8 + (lane >> 2);
                int k = kk + (lane & 3);
                bf[an][0] = f2tf32(Bb[k * 72 + col]);
                bf[an][1] = f2tf32(Bb[(k + 4) * 72 + col]);
            }
#pragma unroll
            for (int am = 0; am < 2; am++)
#pragma unroll
                for (int an = 0; an < 4; an++)
                    MMA_TF32(acc[am][an], af[am][0], af[am][1], af[am][2], af[am][3],
                             bf[an][0], bf[an][1]);
        }
        __syncthreads();
    }

#pragma unroll
    for (int am = 0; am < 2; am++) {
#pragma unroll
        for (int an = 0; an < 4; an++) {
            int row = m0 + wm * 32 + am * 16 + (lane >> 2);
            int col = n0 + wn * 32 + an * 8 + ((lane & 3) << 1);
            float b0 = bias[col], b1 = bias[col + 1];
#pragma unroll
            for (int h = 0; h < 2; h++) {
                int m = row + h * 8;
                float v0 = apply_act(acc[am][an][h * 2 + 0] + b0, ACT);
                float v1 = apply_act(acc[am][an][h * 2 + 1] + b1, ACT);
                if (HASRES) {
                    float2 rr = *(const float2*)(res + (size_t)m * N + col);
                    v0 += rr.x; v1 += rr.y;
                }
                if (HASPOS) {
                    float2 pp = *(const float2*)(pos + (size_t)(m & 511) * N + col);
                    v0 += pp.x; v1 += pp.y;
                }
                *(float2*)(C + (size_t)m * N + col) = make_float2(v0, v1);
            }
        }
    }
}

// ===========================================================================
// fp32 SGEMM 64x64x16, 128 threads — final out projection (precision margin).
// ===========================================================================
__global__ __launch_bounds__(128) void sgemm64_k(
    const float* __restrict__ A, const float* __restrict__ W,
    const float* __restrict__ bias, float* __restrict__ C,
    int M, int N, int K)
{
    __shared__ float As[16][64];
    __shared__ float Bs[16][64];

    int tid = threadIdx.x;
    int bm = blockIdx.y * 64;
    int bn = blockIdx.x * 64;
    int ty = tid >> 3, tx = tid & 7;
    int m0 = ty * 4, n0 = tx * 8;

    float acc[4][8] = {};

    int arow = tid >> 2, acol = (tid & 3) * 4;
    int brow = tid >> 4, bcol = (tid & 15) * 4;

    for (int k0 = 0; k0 < K; k0 += 16) {
#pragma unroll
        for (int r = 0; r < 2; r++) {
            float4 av = *(const float4*)(A + (size_t)(bm + arow + r * 32) * K + k0 + acol);
            As[acol + 0][arow + r * 32] = av.x;
            As[acol + 1][arow + r * 32] = av.y;
            As[acol + 2][arow + r * 32] = av.z;
            As[acol + 3][arow + r * 32] = av.w;
            float4 bv = *(const float4*)(W + (size_t)(k0 + brow + r * 8) * N + bn + bcol);
            *(float4*)(&Bs[brow + r * 8][bcol]) = bv;
        }
        __syncthreads();

#pragma unroll
        for (int k = 0; k < 16; k++) {
            float a[4], b[8];
#pragma unroll
            for (int i = 0; i < 4; i++) a[i] = As[k][m0 + i];
#pragma unroll
            for (int j = 0; j < 8; j++) b[j] = Bs[k][n0 + j];
#pragma unroll
            for (int i = 0; i < 4; i++)
#pragma unroll
                for (int j = 0; j < 8; j++)
                    acc[i][j] = fmaf(a[i], b[j], acc[i][j]);
        }
        __syncthreads();
    }

#pragma unroll
    for (int i = 0; i < 4; i++) {
        int m = bm + m0 + i;
#pragma unroll
        for (int j = 0; j < 8; j++) {
            int n = bn + n0 + j;
            C[(size_t)m * N + n] = acc[i][j] + bias[n];
        }
    }
}

// ===========================================================================
// LayerNorm D=256: one warp per row, 8 rows/block, shuffle-only.
// ===========================================================================
__global__ __launch_bounds__(256) void layernorm8_k(
    const float* __restrict__ x, const float* __restrict__ g,
    const float* __restrict__ b, float* __restrict__ y)
{
    int w = threadIdx.x >> 5, lane = threadIdx.x & 31;
    size_t r = (size_t)blockIdx.x * 8 + w;
    const float4* xp = (const float4*)(x + r * 256);
    float4 v0 = xp[lane];
    float4 v1 = xp[lane + 32];

    float s = v0.x + v0.y + v0.z + v0.w + v1.x + v1.y + v1.z + v1.w;
#pragma unroll
    for (int o = 16; o > 0; o >>= 1) s += __shfl_xor_sync(0xffffffffu, s, o);
    float mean = s * (1.0f / 256.0f);

    float d0x = v0.x - mean, d0y = v0.y - mean, d0z = v0.z - mean, d0w = v0.w - mean;
    float d1x = v1.x - mean, d1y = v1.y - mean, d1z = v1.z - mean, d1w = v1.w - mean;
    float ss = d0x * d0x + d0y * d0y + d0z * d0z + d0w * d0w
             + d1x * d1x + d1y * d1y + d1z * d1z + d1w * d1w;
#pragma unroll
    for (int o = 16; o > 0; o >>= 1) ss += __shfl_xor_sync(0xffffffffu, ss, o);
    float inv = rsqrtf(ss * (1.0f / 256.0f) + 1e-5f);

    float4 g0 = ((const float4*)g)[lane], g1 = ((const float4*)g)[lane + 32];
    float4 b0 = ((const float4*)b)[lane], b1 = ((const float4*)b)[lane + 32];
    float4* yp = (float4*)(y + r * 256);
    yp[lane] = make_float4(d0x * inv * g0.x + b0.x, d0y * inv * g0.y + b0.y,
                           d0z * inv * g0.z + b0.z, d0w * inv * g0.w + b0.w);
    yp[lane + 32] = make_float4(d1x * inv * g1.x + b1.x, d1y * inv * g1.y + b1.y,
                                d1z * inv * g1.z + b1.z, d1w * inv * g1.w + b1.w);
}

// ===========================================================================
// Flash attention
// ===========================================================================
__global__ __launch_bounds__(128) void attn2_k(const float* __restrict__ c,
                                               float* __restrict__ x)
{
    const int S = 512, TD = 768;
    __shared__ float Ks[128][36];
    __shared__ float Vs[128][36];

    int qt  = blockIdx.x;
    int bh  = blockIdx.y;
    int b   = bh >> 3;
    int h   = bh & 7;
    int tid = threadIdx.x;
    int i   = qt * 128 + tid;

    const float* base = c + (size_t)(b * S) * TD;
    const float scale = 0.17677669529663687f;

    float4 q[8];
    {
        const float4* qp = (const float4*)(base + (size_t)i * TD + h * 32);
#pragma unroll
        for (int d = 0; d < 8; d++) q[d] = qp[d];
    }

    float m = -1e30f, l = 0.0f;
    float4 acc[8];
#pragma unroll
    for (int d = 0; d < 8; d++) acc[d] = make_float4(0.f, 0.f, 0.f, 0.f);

    for (int kt = 0; kt <= qt; kt++) {
        int jbase = kt * 128;
        {
            const float4* kp = (const float4*)(base + (size_t)(jbase + tid) * TD + 256 + h * 32);
            const float4* vp = (const float4*)(base + (size_t)(jbase + tid) * TD + 512 + h * 32);
            float4* kd = (float4*)&Ks[tid][0];
            float4* vd = (float4*)&Vs[tid][0];
#pragma unroll
            for (int d = 0; d < 8; d++) { kd[d] = kp[d]; vd[d] = vp[d]; }
        }
        __syncthreads();

        int jmax = (kt == qt) ? tid : 127;
        for (int jj = 0; jj <= jmax; jj++) {
            const float4* kr = (const float4*)&Ks[jj][0];
            float s = 0.0f;
#pragma unroll
            for (int d = 0; d < 8; d++) {
                float4 kv = kr[d];
                s = fmaf(q[d].x, kv.x, s);
                s = fmaf(q[d].y, kv.y, s);
                s = fmaf(q[d].z, kv.z, s);
                s = fmaf(q[d].w, kv.w, s);
            }
            s *= scale;
            const float4* vr = (const float4*)&Vs[jj][0];
            if (s <= m) {
                float p = __expf(s - m);
                l += p;
#pragma unroll
                for (int d = 0; d < 8; d++) {
                    float4 vv = vr[d];
                    acc[d].x = fmaf(p, vv.x, acc[d].x);
                    acc[d].y = fmaf(p, vv.y, acc[d].y);
                    acc[d].z = fmaf(p, vv.z, acc[d].z);
                    acc[d].w = fmaf(p, vv.w, acc[d].w);
                }
            } else {
                float corr = __expf(m - s);
                l = fmaf(l, corr, 1.0f);
#pragma unroll
                for (int d = 0; d < 8; d++) {
                    float4 vv = vr[d];
                    acc[d].x = fmaf(acc[d].x, corr, vv.x);
                    acc[d].y = fmaf(acc[d].y, corr, vv.y);
                    acc[d].z = fmaf(acc[d].z, corr, vv.z);
                    acc[d].w = fmaf(acc[d].w, corr, vv.w);
                }
                m = s;
            }
        }
        __syncthreads();
    }

    float inv = 1.0f / l;
    float4* xp = (float4*)(x + (size_t)(b * S + i) * 256 + h * 32);
#pragma unroll
    for (int d = 0; d < 8; d++) {
        float4 o = xp[d];
        o.x += acc[d].x * inv;
        o.y += acc[d].y * inv;
        o.z += acc[d].z * inv;
        o.w += acc[d].w * inv;
        xp[d] = o;
    }
}

// ===========================================================================
// Global standardization
// ===========================================================================
__global__ void zero_stats_k() { g_sum_d = 0.0; g_sumsq_d = 0.0; }

__global__ void stats_k(const float* __restrict__ e, int n)
{
    double s = 0.0, ss = 0.0;
    for (int i = blockIdx.x * blockDim.x + threadIdx.x; i < n;
         i += gridDim.x * blockDim.x) {
        double v = (double)e[i];
        s += v;
        ss += v * v;
    }
    for (int o = 16; o > 0; o >>= 1) {
        s  += __shfl_xor_sync(0xffffffffu, s, o);
        ss += __shfl_xor_sync(0xffffffffu, ss, o);
    }
    __shared__ double rs[8], rss[8];
    int w = threadIdx.x >> 5, lid = threadIdx.x & 31;
    if (lid == 0) { rs[w] = s; rss[w] = ss; }
    __syncthreads();
    if (threadIdx.x == 0) {
        double S = 0.0, SS = 0.0;
        int nw = blockDim.x >> 5;
        for (int i = 0; i < nw; i++) { S += rs[i]; SS += rss[i]; }
        atomicAdd(&g_sum_d, S);
        atomicAdd(&g_sumsq_d, SS);
    }
}

__global__ void normfinal_k(float* e, int n)
{
    double mean = g_sum_d / (double)n;
    double var = (g_sumsq_d - (double)n * mean * mean) / (double)(n - 1);
    double inv = rsqrt(var);
    for (int i = blockIdx.x * blockDim.x + threadIdx.x; i < n;
         i += gridDim.x * blockDim.x) {
        e[i] = (float)(((double)e[i] - mean) * inv + 1e-10);
    }
}

// ===========================================================================
extern "C" void kernel_launch(void* const* d_in, const int* in_sizes, int n_in,
                              void* d_out, int out_size)
{
    const float* state = (const float*)d_in[0];
    const float* fc1w = (const float*)d_in[1];
    const float* fc1b = (const float*)d_in[2];
    const float* fc2w = (const float*)d_in[3];
    const float* fc2b = (const float*)d_in[4];
    const float* fc3w = (const float*)d_in[5];
    const float* fc3b = (const float*)d_in[6];
    const float* fc4w = (const float*)d_in[7];
    const float* fc4b = (const float*)d_in[8];
    const float* fc5w = (const float*)d_in[9];
    const float* fc5b = (const float*)d_in[10];
    const float* prew = (const float*)d_in[11];
    const float* preb = (const float*)d_in[12];
    const float* posw = (const float*)d_in[13];
    const float* encw = (const float*)d_in[14];
    const float* encb = (const float*)d_in[15];
    const float* ln1g = (const float*)d_in[16];
    const float* ln1b = (const float*)d_in[17];
    const float* ln2g = (const float*)d_in[18];
    const float* ln2b = (const float*)d_in[19];
    const float* rw1  = (const float*)d_in[20];
    const float* rb1  = (const float*)d_in[21];
    const float* rw2  = (const float*)d_in[22];
    const float* rb2  = (const float*)d_in[23];
    const float* outw = (const float*)d_in[24];
    const float* outb = (const float*)d_in[25];
    float* out = (float*)d_out;

    float *ga, *gb, *gx, *gxn, *gc, *gh;
    cudaGetSymbolAddress((void**)&ga,  g_a);
    cudaGetSymbolAddress((void**)&gb,  g_b);
    cudaGetSymbolAddress((void**)&gx,  g_x);
    cudaGetSymbolAddress((void**)&gxn, g_xn);
    cudaGetSymbolAddress((void**)&gc,  g_c);
    cudaGetSymbolAddress((void**)&gh,  g_h);

    const int M = 4096;
    const int SM128 = (2 * 128 * 36 + 2 * 32 * 136) * 4;  // 71680
    const int SM64  = (2 * 64  * 36 + 2 * 32 * 136) * 4;  // 53248
    const int SMS   = (2 * 64  * 36 + 2 * 32 * 72) * 4;   // 36864

    cudaFuncSetAttribute(tgemm_k<128,1,false,false>, cudaFuncAttributeMaxDynamicSharedMemorySize, SM128);
    cudaFuncSetAttribute(tgemm_k<128,3,false,false>, cudaFuncAttributeMaxDynamicSharedMemorySize, SM128);
    cudaFuncSetAttribute(tgemm_k<64,1,false,false>,  cudaFuncAttributeMaxDynamicSharedMemorySize, SM64);
    cudaFuncSetAttribute(tgemm_k<64,0,false,false>,  cudaFuncAttributeMaxDynamicSharedMemorySize, SM64);
    cudaFuncSetAttribute(tgemm_s<2,false,false>,     cudaFuncAttributeMaxDynamicSharedMemorySize, SMS);
    cudaFuncSetAttribute(tgemm_s<0,false,true>,      cudaFuncAttributeMaxDynamicSharedMemorySize, SMS);
    cudaFuncSetAttribute(tgemm_s<0,true,false>,      cudaFuncAttributeMaxDynamicSharedMemorySize, SMS);

    // MLP funnel
    tgemm_k<128,1,false,false><<<dim3(32, 32), 256, SM128>>>(state, fc1w, fc1b, nullptr, nullptr, ga, M, 4096, 4096);
    tgemm_k<128,1,false,false><<<dim3(16, 32), 256, SM128>>>(ga, fc2w, fc2b, nullptr, nullptr, gb, M, 2048, 4096);
    tgemm_k<128,1,false,false><<<dim3(8, 32), 256, SM128>>>(gb, fc3w, fc3b, nullptr, nullptr, ga, M, 1024, 2048);
    tgemm_k<64,1,false,false><<<dim3(4, 64), 256, SM64>>>(ga, fc4w, fc4b, nullptr, nullptr, gb, M, 512, 1024);
    tgemm_s<2,false,false><<<dim3(4, 64), 128, SMS>>>(gb, fc5w, fc5b, nullptr, nullptr, ga, M, 256, 512);
    tgemm_s<0,false,true><<<dim3(4, 64), 128, SMS>>>(ga, prew, preb, nullptr, posw, gx, M, 256, 256);

    for (int l = 0; l < 8; l++) {
        layernorm8_k<<<512, 256>>>(gx, ln1g + l * 256, ln1b + l * 256, gxn);
        tgemm_k<64,0,false,false><<<dim3(6, 64), 256, SM64>>>(gxn, encw + (size_t)l * 256 * 768,
                                                              encb + l * 768, nullptr, nullptr, gc, M, 768, 256);
        attn2_k<<<dim3(4, 64), 128>>>(gc, gx);
        layernorm8_k<<<512, 256>>>(gx, ln2g + l * 256, ln2b + l * 256, gx);
        tgemm_k<128,3,false,false><<<dim3(8, 32), 256, SM128>>>(gx, rw1 + (size_t)l * 256 * 1024,
                                                                rb1 + l * 1024, nullptr, nullptr, gh, M, 1024, 256);
        tgemm_s<0,true,false><<<dim3(4, 64), 128, SMS>>>(gh, rw2 + (size_t)l * 1024 * 256,
                                                         rb2 + l * 256, gx, nullptr, gx, M, 256, 1024);
    }

    // final projection in fp32 (precision margin), then global standardize
    sgemm64_k<<<dim3(2, 64), 128>>>(gx, outw, outb, out, M, 128, 256);
    zero_stats_k<<<1, 1>>>();
    stats_k<<<512, 256>>>(out, 4096 * 128);
    normfinal_k<<<512, 256>>>(out, 4096 * 128);
}